// round 7
// baseline (speedup 1.0000x reference)
#include <cuda_runtime.h>

#define DEPTH   15
#define HDIM    128
#define XDIM    128
#define K2      256
#define NNODES  ((1 << DEPTH) - 1)
#define LEAVES  (1 << (DEPTH - 1))
#define KTL     16   // leaf k-tile
#define KTV     8    // level k-tile

__device__ __forceinline__ unsigned long long pk2(float x, float y) {
    unsigned long long r;
    asm("mov.b64 %0, {%1, %2};" : "=l"(r) : "f"(x), "f"(y));
    return r;
}
__device__ __forceinline__ void upk2(unsigned long long v, float& x, float& y) {
    asm("mov.b64 {%0, %1}, %2;" : "=f"(x), "=f"(y) : "l"(v));
}
__device__ __forceinline__ void fma2(unsigned long long& c, unsigned long long a,
                                     unsigned long long b) {
    asm("fma.rn.f32x2 %0, %1, %2, %0;" : "+l"(c) : "l"(a), "l"(b));
}
__device__ __forceinline__ float sigf(float x)      { return 1.0f / (1.0f + __expf(-x)); }
__device__ __forceinline__ float tanh_fast(float x) { return 2.0f / (1.0f + __expf(-2.0f * x)) - 1.0f; }

__device__ __forceinline__ void cpa16(float* dst, const float* src) {
    unsigned d = (unsigned)__cvta_generic_to_shared(dst);
    asm volatile("cp.async.ca.shared.global [%0], [%1], 16;" :: "r"(d), "l"(src));
}
#define CP_COMMIT() asm volatile("cp.async.commit_group;")
#define CP_WAIT0()  asm volatile("cp.async.wait_group 0;" ::: "memory")

// ---------------- leaf: h_leaf = (1-sig(a_lo))*tanh(a_hi), a = x@Ww + Wb ----
// smem: xs 32KB + ws 32KB = 64KB -> 2+ CTAs/SM. Epilogue pairs cols c / c+128
// via shfl_xor(16) and stores directly (no staging buffer).
__global__ void __launch_bounds__(256, 2)
leaf_kernel(float* __restrict__ h, const float* __restrict__ x,
            const float* __restrict__ Ww, const float* __restrict__ Wb, int R)
{
    extern __shared__ float sm[];
    float* xs = sm;                 // 64*128
    float* ws = sm + 64 * XDIM;     // 2*16*256
    const int tid = threadIdx.x;
    const int rbase = blockIdx.x * 64;

    #pragma unroll
    for (int j = 0; j < 4; j++) cpa16(ws + tid * 4 + j * 1024, Ww + tid * 4 + j * 1024);
    CP_COMMIT();

    for (int idx = tid; idx < 64 * 32; idx += 256) {
        int r = idx >> 5, seg = idx & 31, rg = rbase + r;
        float4 v = make_float4(0.f, 0.f, 0.f, 0.f);
        if (rg < R) {
            int b = rg >> (DEPTH - 1), leaf = rg & (LEAVES - 1);
            v = *(const float4*)(x + ((size_t)b * NNODES + (LEAVES - 1) + leaf) * XDIM + seg * 4);
        }
        *(float4*)(xs + r * XDIM + seg * 4) = v;
    }

    const int tx = tid & 31, ty = tid >> 5;
    unsigned long long acc[8][4];
    #pragma unroll
    for (int r = 0; r < 8; r++)
        #pragma unroll
        for (int c = 0; c < 4; c++) acc[r][c] = 0ULL;

    const int NT = XDIM / KTL;  // 8
    for (int kt = 0; kt < NT; kt++) {
        CP_WAIT0();
        __syncthreads();
        if (kt + 1 < NT) {
            const float* src = Ww + (kt + 1) * KTL * K2;
            float* dst = ws + ((kt + 1) & 1) * (KTL * K2);
            #pragma unroll
            for (int j = 0; j < 4; j++) cpa16(dst + tid * 4 + j * 1024, src + tid * 4 + j * 1024);
            CP_COMMIT();
        }
        const float* w = ws + (kt & 1) * (KTL * K2);
        #pragma unroll
        for (int k = 0; k < KTL; k++) {
            unsigned long long w0 = *(const unsigned long long*)(w + k * K2 + tx * 8);
            unsigned long long w1 = *(const unsigned long long*)(w + k * K2 + tx * 8 + 2);
            unsigned long long w2 = *(const unsigned long long*)(w + k * K2 + tx * 8 + 4);
            unsigned long long w3 = *(const unsigned long long*)(w + k * K2 + tx * 8 + 6);
            #pragma unroll
            for (int r = 0; r < 8; r++) {
                float a = xs[(ty * 8 + r) * XDIM + kt * KTL + k];
                unsigned long long aa = pk2(a, a);
                fma2(acc[r][0], aa, w0); fma2(acc[r][1], aa, w1);
                fma2(acc[r][2], aa, w2); fma2(acc[r][3], aa, w3);
            }
        }
    }

    float bias[8];
    #pragma unroll
    for (int c = 0; c < 8; c++) bias[c] = Wb[tx * 8 + c];
    #pragma unroll
    for (int r = 0; r < 8; r++) {
        float v[8], p[8];
        #pragma unroll
        for (int c = 0; c < 4; c++) upk2(acc[r][c], v[2 * c], v[2 * c + 1]);
        #pragma unroll
        for (int c = 0; c < 8; c++) v[c] += bias[c];
        #pragma unroll
        for (int c = 0; c < 8; c++) p[c] = __shfl_xor_sync(0xffffffffu, v[c], 16);
        int rg = rbase + ty * 8 + r;
        if (tx < 16 && rg < R) {
            float o[8];
            #pragma unroll
            for (int c = 0; c < 8; c++) o[c] = (1.f - sigf(v[c])) * tanh_fast(p[c]);
            int b = rg >> (DEPTH - 1), leaf = rg & (LEAVES - 1);
            float* dst = h + ((size_t)b * NNODES + (LEAVES - 1) + leaf) * HDIM + tx * 8;
            ((float4*)dst)[0] = make_float4(o[0], o[1], o[2], o[3]);
            ((float4*)dst)[1] = make_float4(o[4], o[5], o[6], o[7]);
        }
    }
}

// ---------------- one tree level ------------------------------------------
// phase 1: f = sigmoid(hc @ Ufw + Ufb); overwrite hc with g = f*hc; store
//          s[col<128] = f[col] + f[col+128]  (partner f via shfl_xor 16)
// phase 2: cand = tanh(g @ Uhw + Uhb); h_new = cand*(1-s) + g1 + g2
// smem BM=64: g 64KB + s 32KB + ws 16KB = 112KB -> 2 CTAs/SM.
template<int BM>
__global__ void __launch_bounds__(256, 2)
level_kernel(float* __restrict__ h,
             const float* __restrict__ Ufw, const float* __restrict__ Ufb,
             const float* __restrict__ Uhw, const float* __restrict__ Uhb,
             int l, int R)
{
    const int cnt = 1 << l, start = cnt - 1;
    extern __shared__ float sm[];
    float* gbuf = sm;                        // BM*256 (hc, later g)
    float* sbuf = sm + BM * K2;              // BM*128
    float* ws   = sm + BM * K2 + BM * HDIM;  // 2*KTV*256
    const int tid = threadIdx.x;
    const int rbase = blockIdx.x * BM;

    #pragma unroll
    for (int j = 0; j < 2; j++) cpa16(ws + tid * 4 + j * 1024, Ufw + tid * 4 + j * 1024);
    CP_COMMIT();

    for (int idx = tid; idx < BM * 64; idx += 256) {
        int r = idx >> 6, seg = idx & 63, rg = rbase + r;
        float4 v = make_float4(0.f, 0.f, 0.f, 0.f);
        if (rg < R) {
            int b = rg >> l, i = rg & (cnt - 1);
            v = *(const float4*)(h + ((size_t)b * NNODES + (size_t)2 * (start + i) + 1) * HDIM + seg * 4);
        }
        *(float4*)(gbuf + r * K2 + seg * 4) = v;
    }

    // ---- phase 1 ----
    {
        const int tx = tid & 31, ty = tid >> 5;
        constexpr int TM = BM / 8;
        unsigned long long acc[TM][4];
        #pragma unroll
        for (int r = 0; r < TM; r++)
            #pragma unroll
            for (int c = 0; c < 4; c++) acc[r][c] = 0ULL;

        const int NT = K2 / KTV;  // 32
        for (int kt = 0; kt < NT; kt++) {
            CP_WAIT0();
            __syncthreads();
            if (kt + 1 < NT) {
                const float* src = Ufw + (kt + 1) * KTV * K2;
                float* dst = ws + ((kt + 1) & 1) * (KTV * K2);
                #pragma unroll
                for (int j = 0; j < 2; j++) cpa16(dst + tid * 4 + j * 1024, src + tid * 4 + j * 1024);
                CP_COMMIT();
            }
            const float* w = ws + (kt & 1) * (KTV * K2);
            #pragma unroll
            for (int k = 0; k < KTV; k++) {
                unsigned long long w0 = *(const unsigned long long*)(w + k * K2 + tx * 8);
                unsigned long long w1 = *(const unsigned long long*)(w + k * K2 + tx * 8 + 2);
                unsigned long long w2 = *(const unsigned long long*)(w + k * K2 + tx * 8 + 4);
                unsigned long long w3 = *(const unsigned long long*)(w + k * K2 + tx * 8 + 6);
                #pragma unroll
                for (int r = 0; r < TM; r++) {
                    float a = gbuf[(ty * TM + r) * K2 + kt * KTV + k];
                    unsigned long long aa = pk2(a, a);
                    fma2(acc[r][0], aa, w0); fma2(acc[r][1], aa, w1);
                    fma2(acc[r][2], aa, w2); fma2(acc[r][3], aa, w3);
                }
            }
        }
        __syncthreads();   // everyone done reading hc before we overwrite with g

        // prefetch Uhw tile 0 (overlaps epilogue)
        cpa16(ws + tid * 4, Uhw + tid * 4);
        CP_COMMIT();

        float bias[8];
        #pragma unroll
        for (int c = 0; c < 8; c++) bias[c] = Ufb[tx * 8 + c];
        #pragma unroll
        for (int r = 0; r < TM; r++) {
            int row = ty * TM + r;
            float v[8], p[8];
            #pragma unroll
            for (int c = 0; c < 4; c++) upk2(acc[r][c], v[2 * c], v[2 * c + 1]);
            #pragma unroll
            for (int c = 0; c < 8; c++) v[c] = sigf(v[c] + bias[c]);
            #pragma unroll
            for (int c = 0; c < 8; c++) p[c] = __shfl_xor_sync(0xffffffffu, v[c], 16);
            // g = f * hc  (read-modify-write own 8 cols)
            float4* gp = (float4*)(gbuf + row * K2 + tx * 8);
            float4 h0 = gp[0], h1 = gp[1];
            gp[0] = make_float4(v[0] * h0.x, v[1] * h0.y, v[2] * h0.z, v[3] * h0.w);
            gp[1] = make_float4(v[4] * h1.x, v[5] * h1.y, v[6] * h1.z, v[7] * h1.w);
            if (tx < 16) {
                float4* sp = (float4*)(sbuf + row * HDIM + tx * 8);
                sp[0] = make_float4(v[0] + p[0], v[1] + p[1], v[2] + p[2], v[3] + p[3]);
                sp[1] = make_float4(v[4] + p[4], v[5] + p[5], v[6] + p[6], v[7] + p[7]);
            }
        }
    }

    // ---- phase 2 ----
    {
        const int tx = tid & 15, ty = tid >> 4;
        constexpr int TM2 = BM / 16;
        unsigned long long acc[TM2][4];
        #pragma unroll
        for (int r = 0; r < TM2; r++)
            #pragma unroll
            for (int c = 0; c < 4; c++) acc[r][c] = 0ULL;

        const int NT = K2 / KTV;  // 32
        for (int kt = 0; kt < NT; kt++) {
            CP_WAIT0();
            __syncthreads();   // first iter also publishes g/s writes
            if (kt + 1 < NT) {
                const float* src = Uhw + (kt + 1) * KTV * HDIM;
                float* dst = ws + ((kt + 1) & 1) * (KTV * HDIM);
                cpa16(dst + tid * 4, src + tid * 4);
                CP_COMMIT();
            }
            const float* w = ws + (kt & 1) * (KTV * HDIM);
            #pragma unroll
            for (int k = 0; k < KTV; k++) {
                unsigned long long w0 = *(const unsigned long long*)(w + k * HDIM + tx * 8);
                unsigned long long w1 = *(const unsigned long long*)(w + k * HDIM + tx * 8 + 2);
                unsigned long long w2 = *(const unsigned long long*)(w + k * HDIM + tx * 8 + 4);
                unsigned long long w3 = *(const unsigned long long*)(w + k * HDIM + tx * 8 + 6);
                #pragma unroll
                for (int r = 0; r < TM2; r++) {
                    float a = gbuf[(ty * TM2 + r) * K2 + kt * KTV + k];
                    unsigned long long aa = pk2(a, a);
                    fma2(acc[r][0], aa, w0); fma2(acc[r][1], aa, w1);
                    fma2(acc[r][2], aa, w2); fma2(acc[r][3], aa, w3);
                }
            }
        }

        float bias[8];
        #pragma unroll
        for (int c = 0; c < 8; c++) bias[c] = Uhb[tx * 8 + c];
        #pragma unroll
        for (int r = 0; r < TM2; r++) {
            int row = ty * TM2 + r, rg = rbase + row;
            if (rg >= R) continue;
            float v[8];
            #pragma unroll
            for (int c = 0; c < 4; c++) upk2(acc[r][c], v[2 * c], v[2 * c + 1]);
            const float4* sp = (const float4*)(sbuf + row * HDIM + tx * 8);
            const float4* g1 = (const float4*)(gbuf + row * K2 + tx * 8);
            const float4* g2 = (const float4*)(gbuf + row * K2 + HDIM + tx * 8);
            float4 s0 = sp[0], s1 = sp[1];
            float4 a0 = g1[0], a1 = g1[1], b0 = g2[0], b1 = g2[1];
            float o[8];
            o[0] = tanh_fast(v[0] + bias[0]) * (1.f - s0.x) + a0.x + b0.x;
            o[1] = tanh_fast(v[1] + bias[1]) * (1.f - s0.y) + a0.y + b0.y;
            o[2] = tanh_fast(v[2] + bias[2]) * (1.f - s0.z) + a0.z + b0.z;
            o[3] = tanh_fast(v[3] + bias[3]) * (1.f - s0.w) + a0.w + b0.w;
            o[4] = tanh_fast(v[4] + bias[4]) * (1.f - s1.x) + a1.x + b1.x;
            o[5] = tanh_fast(v[5] + bias[5]) * (1.f - s1.y) + a1.y + b1.y;
            o[6] = tanh_fast(v[6] + bias[6]) * (1.f - s1.z) + a1.z + b1.z;
            o[7] = tanh_fast(v[7] + bias[7]) * (1.f - s1.w) + a1.w + b1.w;
            int b = rg >> l, i = rg & (cnt - 1);
            float* dst = h + ((size_t)b * NNODES + start + i) * HDIM + tx * 8;
            ((float4*)dst)[0] = make_float4(o[0], o[1], o[2], o[3]);
            ((float4*)dst)[1] = make_float4(o[4], o[5], o[6], o[7]);
        }
    }
}

extern "C" void kernel_launch(void* const* d_in, const int* in_sizes, int n_in,
                              void* d_out, int out_size)
{
    const float* x   = (const float*)d_in[0];
    const float* Ww  = (const float*)d_in[1];
    const float* Wb  = (const float*)d_in[2];
    const float* Ufw = (const float*)d_in[3];
    const float* Ufb = (const float*)d_in[4];
    const float* Uhw = (const float*)d_in[5];
    const float* Uhb = (const float*)d_in[6];
    float* h = (float*)d_out;

    const int Btot = (out_size / HDIM) / NNODES;

    const int smem_leaf = (64 * XDIM + 2 * KTL * K2) * (int)sizeof(float);                 // 64 KB
    const int smem_l64  = (64 * K2 + 64 * HDIM + 2 * KTV * K2) * (int)sizeof(float);       // 112 KB
    const int smem_l16  = (16 * K2 + 16 * HDIM + 2 * KTV * K2) * (int)sizeof(float);       // 40 KB

    static bool attr_done = false;
    if (!attr_done) {
        cudaFuncSetAttribute(leaf_kernel,      cudaFuncAttributeMaxDynamicSharedMemorySize, smem_leaf);
        cudaFuncSetAttribute(level_kernel<64>, cudaFuncAttributeMaxDynamicSharedMemorySize, smem_l64);
        cudaFuncSetAttribute(level_kernel<16>, cudaFuncAttributeMaxDynamicSharedMemorySize, smem_l16);
        attr_done = true;
    }

    const int Rleaf = Btot * LEAVES;
    leaf_kernel<<<(Rleaf + 63) / 64, 256, smem_leaf>>>(h, x, Ww, Wb, Rleaf);

    for (int l = DEPTH - 2; l >= 0; l--) {
        int R = Btot << l;
        if (R >= 64)
            level_kernel<64><<<(R + 63) / 64, 256, smem_l64>>>(h, Ufw, Ufb, Uhw, Uhb, l, R);
        else
            level_kernel<16><<<(R + 15) / 16, 256, smem_l16>>>(h, Ufw, Ufb, Uhw, Uhb, l, R);
    }
}

// round 9
// speedup vs baseline: 1.5246x; 1.5246x over previous
#include <cuda_runtime.h>

#define DEPTH   15
#define HDIM    128
#define XDIM    128
#define K2      256
#define NNODES  ((1 << DEPTH) - 1)
#define LEAVES  (1 << (DEPTH - 1))
#define KT      16

__device__ __forceinline__ unsigned long long pk2(float x, float y) {
    unsigned long long r;
    asm("mov.b64 %0, {%1, %2};" : "=l"(r) : "f"(x), "f"(y));
    return r;
}
__device__ __forceinline__ void upk2(unsigned long long v, float& x, float& y) {
    asm("mov.b64 {%0, %1}, %2;" : "=f"(x), "=f"(y) : "l"(v));
}
__device__ __forceinline__ void fma2(unsigned long long& c, unsigned long long a,
                                     unsigned long long b) {
    asm("fma.rn.f32x2 %0, %1, %2, %0;" : "+l"(c) : "l"(a), "l"(b));
}
__device__ __forceinline__ float sigf(float x)      { return 1.0f / (1.0f + __expf(-x)); }
__device__ __forceinline__ float tanh_fast(float x) { return 2.0f / (1.0f + __expf(-2.0f * x)) - 1.0f; }

__device__ __forceinline__ void cpa16(float* dst, const float* src) {
    unsigned d = (unsigned)__cvta_generic_to_shared(dst);
    asm volatile("cp.async.ca.shared.global [%0], [%1], 16;" :: "r"(d), "l"(src));
}
#define CP_COMMIT() asm volatile("cp.async.commit_group;")
#define CP_WAIT0()  asm volatile("cp.async.wait_group 0;" ::: "memory")

// one 16-k GEMM tile step: acts as float4 over k, weights as ulonglong2 pairs
// NCOL_STRIDE: row stride of act buffer; WN: weight row stride (=#cols)
template<int TM, int WN>
__device__ __forceinline__ void gemm_tile16(
    unsigned long long (&acc)[TM][4],
    const float* __restrict__ abuf, int arow0, int astride, int kbase,
    const float* __restrict__ w, int txc)
{
    #pragma unroll
    for (int j = 0; j < 4; j++) {
        float4 a4[TM];
        #pragma unroll
        for (int r = 0; r < TM; r++)
            a4[r] = *(const float4*)(abuf + (arow0 + r) * astride + kbase + j * 4);
        #pragma unroll
        for (int kk = 0; kk < 4; kk++) {
            const float* wk = w + (j * 4 + kk) * WN + txc;
            ulonglong2 wv0 = *(const ulonglong2*)(wk);
            ulonglong2 wv1 = *(const ulonglong2*)(wk + 4);
            #pragma unroll
            for (int r = 0; r < TM; r++) {
                float a = (kk == 0) ? a4[r].x : (kk == 1) ? a4[r].y
                        : (kk == 2) ? a4[r].z : a4[r].w;
                unsigned long long aa = pk2(a, a);
                fma2(acc[r][0], wv0.x, aa); fma2(acc[r][1], wv0.y, aa);
                fma2(acc[r][2], wv1.x, aa); fma2(acc[r][3], wv1.y, aa);
            }
        }
    }
}

// ---------------- leaf: h_leaf = (1-sig(a_lo))*tanh(a_hi), a = x@Ww + Wb ----
__global__ void __launch_bounds__(256, 2)
leaf_kernel(float* __restrict__ h, const float* __restrict__ x,
            const float* __restrict__ Ww, const float* __restrict__ Wb, int R)
{
    extern __shared__ float sm[];
    float* xs = sm;                 // 64*128
    float* ws = sm + 64 * XDIM;     // 2*16*256
    const int tid = threadIdx.x;
    const int rbase = blockIdx.x * 64;

    #pragma unroll
    for (int j = 0; j < 4; j++) cpa16(ws + tid * 4 + j * 1024, Ww + tid * 4 + j * 1024);
    CP_COMMIT();

    for (int idx = tid; idx < 64 * 32; idx += 256) {
        int r = idx >> 5, seg = idx & 31, rg = rbase + r;
        float4 v = make_float4(0.f, 0.f, 0.f, 0.f);
        if (rg < R) {
            int b = rg >> (DEPTH - 1), leaf = rg & (LEAVES - 1);
            v = *(const float4*)(x + ((size_t)b * NNODES + (LEAVES - 1) + leaf) * XDIM + seg * 4);
        }
        *(float4*)(xs + r * XDIM + seg * 4) = v;
    }

    const int tx = tid & 31, ty = tid >> 5;
    unsigned long long acc[8][4];
    #pragma unroll
    for (int r = 0; r < 8; r++)
        #pragma unroll
        for (int c = 0; c < 4; c++) acc[r][c] = 0ULL;

    const int NT = XDIM / KT;  // 8
    for (int kt = 0; kt < NT; kt++) {
        CP_WAIT0();
        __syncthreads();
        if (kt + 1 < NT) {
            const float* src = Ww + (kt + 1) * KT * K2;
            float* dst = ws + ((kt + 1) & 1) * (KT * K2);
            #pragma unroll
            for (int j = 0; j < 4; j++) cpa16(dst + tid * 4 + j * 1024, src + tid * 4 + j * 1024);
            CP_COMMIT();
        }
        gemm_tile16<8, K2>(acc, xs, ty * 8, XDIM, kt * KT,
                           ws + (kt & 1) * (KT * K2), tx * 8);
    }

    float bias[8];
    #pragma unroll
    for (int c = 0; c < 8; c++) bias[c] = Wb[tx * 8 + c];
    #pragma unroll
    for (int r = 0; r < 8; r++) {
        float v[8], p[8];
        #pragma unroll
        for (int c = 0; c < 4; c++) upk2(acc[r][c], v[2 * c], v[2 * c + 1]);
        #pragma unroll
        for (int c = 0; c < 8; c++) v[c] += bias[c];
        #pragma unroll
        for (int c = 0; c < 8; c++) p[c] = __shfl_xor_sync(0xffffffffu, v[c], 16);
        int rg = rbase + ty * 8 + r;
        if (tx < 16 && rg < R) {
            float o[8];
            #pragma unroll
            for (int c = 0; c < 8; c++) o[c] = (1.f - sigf(v[c])) * tanh_fast(p[c]);
            int b = rg >> (DEPTH - 1), leaf = rg & (LEAVES - 1);
            float* dst = h + ((size_t)b * NNODES + (LEAVES - 1) + leaf) * HDIM + tx * 8;
            ((float4*)dst)[0] = make_float4(o[0], o[1], o[2], o[3]);
            ((float4*)dst)[1] = make_float4(o[4], o[5], o[6], o[7]);
        }
    }
}

// ---------------- one tree level ------------------------------------------
template<int BM>
__global__ void __launch_bounds__(256, 1)
level_kernel(float* __restrict__ h,
             const float* __restrict__ Ufw, const float* __restrict__ Ufb,
             const float* __restrict__ Uhw, const float* __restrict__ Uhb,
             int l, int R)
{
    const int cnt = 1 << l, start = cnt - 1;
    extern __shared__ float sm[];
    float* gbuf = sm;                        // BM*256 (hc, later g)
    float* sbuf = sm + BM * K2;              // BM*128
    float* ws   = sm + BM * K2 + BM * HDIM;  // 2*16*256
    const int tid = threadIdx.x;
    const int rbase = blockIdx.x * BM;

    #pragma unroll
    for (int j = 0; j < 4; j++) cpa16(ws + tid * 4 + j * 1024, Ufw + tid * 4 + j * 1024);
    CP_COMMIT();

    for (int idx = tid; idx < BM * 64; idx += 256) {
        int r = idx >> 6, seg = idx & 63, rg = rbase + r;
        float4 v = make_float4(0.f, 0.f, 0.f, 0.f);
        if (rg < R) {
            int b = rg >> l, i = rg & (cnt - 1);
            v = *(const float4*)(h + ((size_t)b * NNODES + (size_t)2 * (start + i) + 1) * HDIM + seg * 4);
        }
        *(float4*)(gbuf + r * K2 + seg * 4) = v;
    }

    // ---- phase 1: f = sigmoid(hc@Ufw+Ufb); g = f*hc (in place); s = f1+f2 ----
    {
        const int tx = tid & 31, ty = tid >> 5;
        constexpr int TM = BM / 8;
        unsigned long long acc[TM][4];
        #pragma unroll
        for (int r = 0; r < TM; r++)
            #pragma unroll
            for (int c = 0; c < 4; c++) acc[r][c] = 0ULL;

        const int NT = K2 / KT;  // 16
        for (int kt = 0; kt < NT; kt++) {
            CP_WAIT0();
            __syncthreads();
            if (kt + 1 < NT) {
                const float* src = Ufw + (kt + 1) * KT * K2;
                float* dst = ws + ((kt + 1) & 1) * (KT * K2);
                #pragma unroll
                for (int j = 0; j < 4; j++) cpa16(dst + tid * 4 + j * 1024, src + tid * 4 + j * 1024);
                CP_COMMIT();
            }
            gemm_tile16<TM, K2>(acc, gbuf, ty * TM, K2, kt * KT,
                                ws + (kt & 1) * (KT * K2), tx * 8);
        }
        __syncthreads();   // all reads of hc done before overwriting with g

        // prefetch Uhw tile 0 (8KB -> 2 cpa16/thread), overlaps epilogue
        #pragma unroll
        for (int j = 0; j < 2; j++) cpa16(ws + tid * 4 + j * 1024, Uhw + tid * 4 + j * 1024);
        CP_COMMIT();

        float bias[8];
        #pragma unroll
        for (int c = 0; c < 8; c++) bias[c] = Ufb[tx * 8 + c];
        #pragma unroll
        for (int r = 0; r < TM; r++) {
            int row = ty * TM + r;
            float v[8], p[8];
            #pragma unroll
            for (int c = 0; c < 4; c++) upk2(acc[r][c], v[2 * c], v[2 * c + 1]);
            #pragma unroll
            for (int c = 0; c < 8; c++) v[c] = sigf(v[c] + bias[c]);
            #pragma unroll
            for (int c = 0; c < 8; c++) p[c] = __shfl_xor_sync(0xffffffffu, v[c], 16);
            float4* gp = (float4*)(gbuf + row * K2 + tx * 8);
            float4 h0 = gp[0], h1 = gp[1];
            gp[0] = make_float4(v[0] * h0.x, v[1] * h0.y, v[2] * h0.z, v[3] * h0.w);
            gp[1] = make_float4(v[4] * h1.x, v[5] * h1.y, v[6] * h1.z, v[7] * h1.w);
            if (tx < 16) {
                float4* sp = (float4*)(sbuf + row * HDIM + tx * 8);
                sp[0] = make_float4(v[0] + p[0], v[1] + p[1], v[2] + p[2], v[3] + p[3]);
                sp[1] = make_float4(v[4] + p[4], v[5] + p[5], v[6] + p[6], v[7] + p[7]);
            }
        }
    }

    // ---- phase 2: cand = tanh(g@Uhw+Uhb); h_new = cand*(1-s) + g1 + g2 ----
    {
        const int tx = tid & 15, ty = tid >> 4;
        constexpr int TM2 = BM / 16;
        unsigned long long acc[TM2][4];
        #pragma unroll
        for (int r = 0; r < TM2; r++)
            #pragma unroll
            for (int c = 0; c < 4; c++) acc[r][c] = 0ULL;

        const int NT = K2 / KT;  // 16
        for (int kt = 0; kt < NT; kt++) {
            CP_WAIT0();
            __syncthreads();   // first iter also publishes g/s writes
            if (kt + 1 < NT) {
                const float* src = Uhw + (kt + 1) * KT * HDIM;
                float* dst = ws + ((kt + 1) & 1) * (KT * HDIM);
                #pragma unroll
                for (int j = 0; j < 2; j++) cpa16(dst + tid * 4 + j * 1024, src + tid * 4 + j * 1024);
                CP_COMMIT();
            }
            gemm_tile16<TM2, HDIM>(acc, gbuf, ty * TM2, K2, kt * KT,
                                   ws + (kt & 1) * (KT * HDIM), tx * 8);
        }

        float bias[8];
        #pragma unroll
        for (int c = 0; c < 8; c++) bias[c] = Uhb[tx * 8 + c];
        #pragma unroll
        for (int r = 0; r < TM2; r++) {
            int row = ty * TM2 + r, rg = rbase + row;
            if (rg >= R) continue;
            float v[8];
            #pragma unroll
            for (int c = 0; c < 4; c++) upk2(acc[r][c], v[2 * c], v[2 * c + 1]);
            const float4* sp = (const float4*)(sbuf + row * HDIM + tx * 8);
            const float4* g1 = (const float4*)(gbuf + row * K2 + tx * 8);
            const float4* g2 = (const float4*)(gbuf + row * K2 + HDIM + tx * 8);
            float4 s0 = sp[0], s1 = sp[1];
            float4 a0 = g1[0], a1 = g1[1], b0 = g2[0], b1 = g2[1];
            float o[8];
            o[0] = tanh_fast(v[0] + bias[0]) * (1.f - s0.x) + a0.x + b0.x;
            o[1] = tanh_fast(v[1] + bias[1]) * (1.f - s0.y) + a0.y + b0.y;
            o[2] = tanh_fast(v[2] + bias[2]) * (1.f - s0.z) + a0.z + b0.z;
            o[3] = tanh_fast(v[3] + bias[3]) * (1.f - s0.w) + a0.w + b0.w;
            o[4] = tanh_fast(v[4] + bias[4]) * (1.f - s1.x) + a1.x + b1.x;
            o[5] = tanh_fast(v[5] + bias[5]) * (1.f - s1.y) + a1.y + b1.y;
            o[6] = tanh_fast(v[6] + bias[6]) * (1.f - s1.z) + a1.z + b1.z;
            o[7] = tanh_fast(v[7] + bias[7]) * (1.f - s1.w) + a1.w + b1.w;
            int b = rg >> l, i = rg & (cnt - 1);
            float* dst = h + ((size_t)b * NNODES + start + i) * HDIM + tx * 8;
            ((float4*)dst)[0] = make_float4(o[0], o[1], o[2], o[3]);
            ((float4*)dst)[1] = make_float4(o[4], o[5], o[6], o[7]);
        }
    }
}

extern "C" void kernel_launch(void* const* d_in, const int* in_sizes, int n_in,
                              void* d_out, int out_size)
{
    const float* x   = (const float*)d_in[0];
    const float* Ww  = (const float*)d_in[1];
    const float* Wb  = (const float*)d_in[2];
    const float* Ufw = (const float*)d_in[3];
    const float* Ufb = (const float*)d_in[4];
    const float* Uhw = (const float*)d_in[5];
    const float* Uhb = (const float*)d_in[6];
    float* h = (float*)d_out;

    const int Btot = (out_size / HDIM) / NNODES;

    const int smem_leaf = (64 * XDIM + 2 * KT * K2) * (int)sizeof(float);             // 64 KB
    const int smem_l64  = (64 * K2 + 64 * HDIM + 2 * KT * K2) * (int)sizeof(float);   // 128 KB
    const int smem_l16  = (16 * K2 + 16 * HDIM + 2 * KT * K2) * (int)sizeof(float);   // 56 KB

    static bool attr_done = false;
    if (!attr_done) {
        cudaFuncSetAttribute(leaf_kernel,      cudaFuncAttributeMaxDynamicSharedMemorySize, smem_leaf);
        cudaFuncSetAttribute(level_kernel<64>, cudaFuncAttributeMaxDynamicSharedMemorySize, smem_l64);
        cudaFuncSetAttribute(level_kernel<16>, cudaFuncAttributeMaxDynamicSharedMemorySize, smem_l16);
        attr_done = true;
    }

    const int Rleaf = Btot * LEAVES;
    leaf_kernel<<<(Rleaf + 63) / 64, 256, smem_leaf>>>(h, x, Ww, Wb, Rleaf);

    for (int l = DEPTH - 2; l >= 0; l--) {
        int R = Btot << l;
        if (R >= 64)
            level_kernel<64><<<(R + 63) / 64, 256, smem_l64>>>(h, Ufw, Ufb, Uhw, Uhb, l, R);
        else
            level_kernel<16><<<(R + 15) / 16, 256, smem_l16>>>(h, Ufw, Ufb, Uhw, Uhb, l, R);
    }
}

// round 11
// speedup vs baseline: 1.5683x; 1.0286x over previous
#include <cuda_runtime.h>

#define DEPTH   15
#define HDIM    128
#define XDIM    128
#define K2      256
#define NNODES  ((1 << DEPTH) - 1)
#define LEAVES  (1 << (DEPTH - 1))
#define KT      16

__device__ __forceinline__ unsigned long long pk2(float x, float y) {
    unsigned long long r;
    asm("mov.b64 %0, {%1, %2};" : "=l"(r) : "f"(x), "f"(y));
    return r;
}
__device__ __forceinline__ void upk2(unsigned long long v, float& x, float& y) {
    asm("mov.b64 {%0, %1}, %2;" : "=f"(x), "=f"(y) : "l"(v));
}
__device__ __forceinline__ void fma2(unsigned long long& c, unsigned long long a,
                                     unsigned long long b) {
    asm("fma.rn.f32x2 %0, %1, %2, %0;" : "+l"(c) : "l"(a), "l"(b));
}
__device__ __forceinline__ float sigf(float x)      { return 1.0f / (1.0f + __expf(-x)); }
__device__ __forceinline__ float tanh_fast(float x) { return 2.0f / (1.0f + __expf(-2.0f * x)) - 1.0f; }

__device__ __forceinline__ void cpa16(float* dst, const float* src) {
    unsigned d = (unsigned)__cvta_generic_to_shared(dst);
    asm volatile("cp.async.ca.shared.global [%0], [%1], 16;" :: "r"(d), "l"(src));
}
#define CP_COMMIT() asm volatile("cp.async.commit_group;")
#define CP_WAIT0()  asm volatile("cp.async.wait_group 0;" ::: "memory")

// one 16-k GEMM tile step: acts as float4 over k (broadcast), weights as 2x LDS.128
template<int TM, int WN>
__device__ __forceinline__ void gemm_tile16(
    unsigned long long (&acc)[TM][4],
    const float* __restrict__ abuf, int arow0, int astride, int kbase,
    const float* __restrict__ w, int txc)
{
    #pragma unroll
    for (int j = 0; j < 4; j++) {
        float4 a4[TM];
        #pragma unroll
        for (int r = 0; r < TM; r++)
            a4[r] = *(const float4*)(abuf + (arow0 + r) * astride + kbase + j * 4);
        #pragma unroll
        for (int kk = 0; kk < 4; kk++) {
            const float* wk = w + (j * 4 + kk) * WN + txc;
            ulonglong2 wv0 = *(const ulonglong2*)(wk);
            ulonglong2 wv1 = *(const ulonglong2*)(wk + 4);
            #pragma unroll
            for (int r = 0; r < TM; r++) {
                float a = (kk == 0) ? a4[r].x : (kk == 1) ? a4[r].y
                        : (kk == 2) ? a4[r].z : a4[r].w;
                unsigned long long aa = pk2(a, a);
                fma2(acc[r][0], wv0.x, aa); fma2(acc[r][1], wv0.y, aa);
                fma2(acc[r][2], wv1.x, aa); fma2(acc[r][3], wv1.y, aa);
            }
        }
    }
}

// ---------------- leaf: h_leaf = (1-sig(a_lo))*tanh(a_hi), a = x@Ww + Wb ----
__global__ void __launch_bounds__(256, 2)
leaf_kernel(float* __restrict__ h, const float* __restrict__ x,
            const float* __restrict__ Ww, const float* __restrict__ Wb, int R)
{
    extern __shared__ float sm[];
    float* xs = sm;                 // 64*128
    float* ws = sm + 64 * XDIM;     // 2*16*256
    const int tid = threadIdx.x;
    const int rbase = blockIdx.x * 64;

    #pragma unroll
    for (int j = 0; j < 4; j++) cpa16(ws + tid * 4 + j * 1024, Ww + tid * 4 + j * 1024);
    CP_COMMIT();

    for (int idx = tid; idx < 64 * 32; idx += 256) {
        int r = idx >> 5, seg = idx & 31, rg = rbase + r;
        float4 v = make_float4(0.f, 0.f, 0.f, 0.f);
        if (rg < R) {
            int b = rg >> (DEPTH - 1), leaf = rg & (LEAVES - 1);
            v = *(const float4*)(x + ((size_t)b * NNODES + (LEAVES - 1) + leaf) * XDIM + seg * 4);
        }
        *(float4*)(xs + r * XDIM + seg * 4) = v;
    }

    const int tx = tid & 31, ty = tid >> 5;
    unsigned long long acc[8][4];
    #pragma unroll
    for (int r = 0; r < 8; r++)
        #pragma unroll
        for (int c = 0; c < 4; c++) acc[r][c] = 0ULL;

    const int NT = XDIM / KT;  // 8
    for (int kt = 0; kt < NT; kt++) {
        CP_WAIT0();
        __syncthreads();
        if (kt + 1 < NT) {
            const float* src = Ww + (kt + 1) * KT * K2;
            float* dst = ws + ((kt + 1) & 1) * (KT * K2);
            #pragma unroll
            for (int j = 0; j < 4; j++) cpa16(dst + tid * 4 + j * 1024, src + tid * 4 + j * 1024);
            CP_COMMIT();
        }
        gemm_tile16<8, K2>(acc, xs, ty * 8, XDIM, kt * KT,
                           ws + (kt & 1) * (KT * K2), tx * 8);
    }

    float bias[8];
    #pragma unroll
    for (int c = 0; c < 8; c++) bias[c] = Wb[tx * 8 + c];
    #pragma unroll
    for (int r = 0; r < 8; r++) {
        float v[8], p[8];
        #pragma unroll
        for (int c = 0; c < 4; c++) upk2(acc[r][c], v[2 * c], v[2 * c + 1]);
        #pragma unroll
        for (int c = 0; c < 8; c++) v[c] += bias[c];
        #pragma unroll
        for (int c = 0; c < 8; c++) p[c] = __shfl_xor_sync(0xffffffffu, v[c], 16);
        int rg = rbase + ty * 8 + r;
        if (tx < 16 && rg < R) {
            float o[8];
            #pragma unroll
            for (int c = 0; c < 8; c++) o[c] = (1.f - sigf(v[c])) * tanh_fast(p[c]);
            int b = rg >> (DEPTH - 1), leaf = rg & (LEAVES - 1);
            float* dst = h + ((size_t)b * NNODES + (LEAVES - 1) + leaf) * HDIM + tx * 8;
            ((float4*)dst)[0] = make_float4(o[0], o[1], o[2], o[3]);
            ((float4*)dst)[1] = make_float4(o[4], o[5], o[6], o[7]);
        }
    }
}

// ---------------- one tree level (BM rows, THR threads) --------------------
template<int BM, int THR>
__global__ void __launch_bounds__(THR, 1)
level_kernel(float* __restrict__ h,
             const float* __restrict__ Ufw, const float* __restrict__ Ufb,
             const float* __restrict__ Uhw, const float* __restrict__ Uhb,
             int l, int R)
{
    const int cnt = 1 << l, start = cnt - 1;
    extern __shared__ float sm[];
    float* gbuf = sm;                        // BM*256 (hc, later g)
    float* sbuf = sm + BM * K2;              // BM*128
    float* ws   = sm + BM * K2 + BM * HDIM;  // 2*16*256
    const int tid = threadIdx.x;
    const int rbase = blockIdx.x * BM;

    constexpr int CPW1 = (KT * K2 / 4) / THR;   // float4s per thread, 16KB tile
    constexpr int CPW2 = (KT * HDIM / 4) / THR; // 8KB tile

    #pragma unroll
    for (int j = 0; j < CPW1; j++)
        cpa16(ws + (tid + j * THR) * 4, Ufw + (tid + j * THR) * 4);
    CP_COMMIT();

    for (int idx = tid; idx < BM * 64; idx += THR) {
        int r = idx >> 6, seg = idx & 63, rg = rbase + r;
        float4 v = make_float4(0.f, 0.f, 0.f, 0.f);
        if (rg < R) {
            int b = rg >> l, i = rg & (cnt - 1);
            v = *(const float4*)(h + ((size_t)b * NNODES + (size_t)2 * (start + i) + 1) * HDIM + seg * 4);
        }
        *(float4*)(gbuf + r * K2 + seg * 4) = v;
    }

    // ---- phase 1: f = sigmoid(hc@Ufw+Ufb); g = f*hc (in place); s = f1+f2 ----
    {
        const int tx = tid & 31, ty = tid >> 5;
        constexpr int TM = BM / (THR / 32);
        unsigned long long acc[TM][4];
        #pragma unroll
        for (int r = 0; r < TM; r++)
            #pragma unroll
            for (int c = 0; c < 4; c++) acc[r][c] = 0ULL;

        const int NT = K2 / KT;  // 16
        for (int kt = 0; kt < NT; kt++) {
            CP_WAIT0();
            __syncthreads();
            if (kt + 1 < NT) {
                const float* src = Ufw + (kt + 1) * KT * K2;
                float* dst = ws + ((kt + 1) & 1) * (KT * K2);
                #pragma unroll
                for (int j = 0; j < CPW1; j++)
                    cpa16(dst + (tid + j * THR) * 4, src + (tid + j * THR) * 4);
                CP_COMMIT();
            }
            gemm_tile16<TM, K2>(acc, gbuf, ty * TM, K2, kt * KT,
                                ws + (kt & 1) * (KT * K2), tx * 8);
        }
        __syncthreads();   // all reads of hc done before overwriting with g

        // prefetch Uhw tile 0 (overlaps epilogue)
        #pragma unroll
        for (int j = 0; j < CPW2; j++)
            cpa16(ws + (tid + j * THR) * 4, Uhw + (tid + j * THR) * 4);
        CP_COMMIT();

        float bias[8];
        #pragma unroll
        for (int c = 0; c < 8; c++) bias[c] = Ufb[tx * 8 + c];
        #pragma unroll
        for (int r = 0; r < TM; r++) {
            int row = ty * TM + r;
            float v[8], p[8];
            #pragma unroll
            for (int c = 0; c < 4; c++) upk2(acc[r][c], v[2 * c], v[2 * c + 1]);
            #pragma unroll
            for (int c = 0; c < 8; c++) v[c] = sigf(v[c] + bias[c]);
            #pragma unroll
            for (int c = 0; c < 8; c++) p[c] = __shfl_xor_sync(0xffffffffu, v[c], 16);
            float4* gp = (float4*)(gbuf + row * K2 + tx * 8);
            float4 h0 = gp[0], h1 = gp[1];
            gp[0] = make_float4(v[0] * h0.x, v[1] * h0.y, v[2] * h0.z, v[3] * h0.w);
            gp[1] = make_float4(v[4] * h1.x, v[5] * h1.y, v[6] * h1.z, v[7] * h1.w);
            if (tx < 16) {
                float4* sp = (float4*)(sbuf + row * HDIM + tx * 8);
                sp[0] = make_float4(v[0] + p[0], v[1] + p[1], v[2] + p[2], v[3] + p[3]);
                sp[1] = make_float4(v[4] + p[4], v[5] + p[5], v[6] + p[6], v[7] + p[7]);
            }
        }
    }

    // ---- phase 2: cand = tanh(g@Uhw+Uhb); h_new = cand*(1-s) + g1 + g2 ----
    {
        const int tx = tid & 15, ty = tid >> 4;
        constexpr int TM2 = BM / (THR / 16);
        unsigned long long acc[TM2][4];
        #pragma unroll
        for (int r = 0; r < TM2; r++)
            #pragma unroll
            for (int c = 0; c < 4; c++) acc[r][c] = 0ULL;

        const int NT = K2 / KT;  // 16
        for (int kt = 0; kt < NT; kt++) {
            CP_WAIT0();
            __syncthreads();   // first iter also publishes g/s writes
            if (kt + 1 < NT) {
                const float* src = Uhw + (kt + 1) * KT * HDIM;
                float* dst = ws + ((kt + 1) & 1) * (KT * HDIM);
                #pragma unroll
                for (int j = 0; j < CPW2; j++)
                    cpa16(dst + (tid + j * THR) * 4, src + (tid + j * THR) * 4);
                CP_COMMIT();
            }
            gemm_tile16<TM2, HDIM>(acc, gbuf, ty * TM2, K2, kt * KT,
                                   ws + (kt & 1) * (KT * HDIM), tx * 8);
        }

        float bias[8];
        #pragma unroll
        for (int c = 0; c < 8; c++) bias[c] = Uhb[tx * 8 + c];
        #pragma unroll
        for (int r = 0; r < TM2; r++) {
            int row = ty * TM2 + r, rg = rbase + row;
            if (rg >= R) continue;
            float v[8];
            #pragma unroll
            for (int c = 0; c < 4; c++) upk2(acc[r][c], v[2 * c], v[2 * c + 1]);
            const float4* sp = (const float4*)(sbuf + row * HDIM + tx * 8);
            const float4* g1 = (const float4*)(gbuf + row * K2 + tx * 8);
            const float4* g2 = (const float4*)(gbuf + row * K2 + HDIM + tx * 8);
            float4 s0 = sp[0], s1 = sp[1];
            float4 a0 = g1[0], a1 = g1[1], b0 = g2[0], b1 = g2[1];
            float o[8];
            o[0] = tanh_fast(v[0] + bias[0]) * (1.f - s0.x) + a0.x + b0.x;
            o[1] = tanh_fast(v[1] + bias[1]) * (1.f - s0.y) + a0.y + b0.y;
            o[2] = tanh_fast(v[2] + bias[2]) * (1.f - s0.z) + a0.z + b0.z;
            o[3] = tanh_fast(v[3] + bias[3]) * (1.f - s0.w) + a0.w + b0.w;
            o[4] = tanh_fast(v[4] + bias[4]) * (1.f - s1.x) + a1.x + b1.x;
            o[5] = tanh_fast(v[5] + bias[5]) * (1.f - s1.y) + a1.y + b1.y;
            o[6] = tanh_fast(v[6] + bias[6]) * (1.f - s1.z) + a1.z + b1.z;
            o[7] = tanh_fast(v[7] + bias[7]) * (1.f - s1.w) + a1.w + b1.w;
            int b = rg >> l, i = rg & (cnt - 1);
            float* dst = h + ((size_t)b * NNODES + start + i) * HDIM + tx * 8;
            ((float4*)dst)[0] = make_float4(o[0], o[1], o[2], o[3]);
            ((float4*)dst)[1] = make_float4(o[4], o[5], o[6], o[7]);
        }
    }
}

extern "C" void kernel_launch(void* const* d_in, const int* in_sizes, int n_in,
                              void* d_out, int out_size)
{
    const float* x   = (const float*)d_in[0];
    const float* Ww  = (const float*)d_in[1];
    const float* Wb  = (const float*)d_in[2];
    const float* Ufw = (const float*)d_in[3];
    const float* Ufb = (const float*)d_in[4];
    const float* Uhw = (const float*)d_in[5];
    const float* Uhb = (const float*)d_in[6];
    float* h = (float*)d_out;

    const int Btot = (out_size / HDIM) / NNODES;

    const int smem_leaf = (64 * XDIM + 2 * KT * K2) * (int)sizeof(float);               // 64 KB
    const int smem_l128 = (128 * K2 + 128 * HDIM + 2 * KT * K2) * (int)sizeof(float);   // 224 KB
    const int smem_l16  = (16 * K2 + 16 * HDIM + 2 * KT * K2) * (int)sizeof(float);     // 56 KB

    static bool attr_done = false;
    if (!attr_done) {
        cudaFuncSetAttribute(leaf_kernel,            cudaFuncAttributeMaxDynamicSharedMemorySize, smem_leaf);
        cudaFuncSetAttribute(level_kernel<128, 512>, cudaFuncAttributeMaxDynamicSharedMemorySize, smem_l128);
        cudaFuncSetAttribute(level_kernel<16, 256>,  cudaFuncAttributeMaxDynamicSharedMemorySize, smem_l16);
        attr_done = true;
    }

    const int Rleaf = Btot * LEAVES;
    leaf_kernel<<<(Rleaf + 63) / 64, 256, smem_leaf>>>(h, x, Ww, Wb, Rleaf);

    for (int l = DEPTH - 2; l >= 0; l--) {
        int R = Btot << l;
        if (R >= 2048)
            level_kernel<128, 512><<<(R + 127) / 128, 512, smem_l128>>>(h, Ufw, Ufb, Uhw, Uhb, l, R);
        else
            level_kernel<16, 256><<<(R + 15) / 16, 256, smem_l16>>>(h, Ufw, Ufb, Uhw, Uhb, l, R);
    }
}

// round 14
// speedup vs baseline: 1.9580x; 1.2485x over previous
#include <cuda_runtime.h>

#define DEPTH   15
#define HDIM    128
#define XDIM    128
#define K2      256
#define NNODES  ((1 << DEPTH) - 1)
#define LEAVES  (1 << (DEPTH - 1))
#define KT      16

__device__ __forceinline__ void upk2(unsigned long long v, float& x, float& y) {
    asm("mov.b64 {%0, %1}, %2;" : "=f"(x), "=f"(y) : "l"(v));
}
__device__ __forceinline__ unsigned long long pk2(float x, float y) {
    unsigned long long r;
    asm("mov.b64 %0, {%1, %2};" : "=l"(r) : "f"(x), "f"(y));
    return r;
}
__device__ __forceinline__ void fma2(unsigned long long& c, unsigned long long a,
                                     unsigned long long b) {
    asm("fma.rn.f32x2 %0, %1, %2, %0;" : "+l"(c) : "l"(a), "l"(b));
}
__device__ __forceinline__ float sigf(float x)      { return 1.0f / (1.0f + __expf(-x)); }
__device__ __forceinline__ float tanh_fast(float x) { return 2.0f / (1.0f + __expf(-2.0f * x)) - 1.0f; }

__device__ __forceinline__ void cpa16(float* dst, const float* src) {
    unsigned d = (unsigned)__cvta_generic_to_shared(dst);
    asm volatile("cp.async.ca.shared.global [%0], [%1], 16;" :: "r"(d), "l"(src));
}
#define CP_COMMIT() asm volatile("cp.async.commit_group;")
#define CP_WAIT0()  asm volatile("cp.async.wait_group 0;" ::: "memory")

// one 16-k GEMM tile: acts broadcast as float4 over k; weights as two DENSE
// 16B groups per thread (cols c0=tx*4 and c1=WN/2+tx*4) -> conflict-free LDS.
// acc[r][0]=(c0,c0+1) acc[r][1]=(c0+2,c0+3) acc[r][2]=(c1,c1+1) acc[r][3]=(c1+2,c1+3)
template<int TM, int WN>
__device__ __forceinline__ void gemm_tile16(
    unsigned long long (&acc)[TM][4],
    const float* __restrict__ abuf, int arow0, int astride, int kbase,
    const float* __restrict__ w, int c0)
{
    const int c1 = WN / 2 + c0;
    #pragma unroll
    for (int j = 0; j < 4; j++) {
        float4 a4[TM];
        #pragma unroll
        for (int r = 0; r < TM; r++)
            a4[r] = *(const float4*)(abuf + (arow0 + r) * astride + kbase + j * 4);
        #pragma unroll
        for (int kk = 0; kk < 4; kk++) {
            const float* wk = w + (j * 4 + kk) * WN;
            ulonglong2 wa = *(const ulonglong2*)(wk + c0);
            ulonglong2 wb = *(const ulonglong2*)(wk + c1);
            #pragma unroll
            for (int r = 0; r < TM; r++) {
                float a = (kk == 0) ? a4[r].x : (kk == 1) ? a4[r].y
                        : (kk == 2) ? a4[r].z : a4[r].w;
                unsigned long long aa = pk2(a, a);
                fma2(acc[r][0], wa.x, aa); fma2(acc[r][1], wa.y, aa);
                fma2(acc[r][2], wb.x, aa); fma2(acc[r][3], wb.y, aa);
            }
        }
    }
}

// ---------------- leaf: h_leaf = (1-sig(a_lo))*tanh(a_hi), a = x@Ww + Wb ----
// thread owns cols tx*4 (f0 part) and 128+tx*4 (c0 part) -> pure-local epilogue
__global__ void __launch_bounds__(256, 2)
leaf_kernel(float* __restrict__ h, const float* __restrict__ x,
            const float* __restrict__ Ww, const float* __restrict__ Wb, int R)
{
    extern __shared__ float sm[];
    float* xs = sm;                 // 64*128
    float* ws = sm + 64 * XDIM;     // 2*16*256
    const int tid = threadIdx.x;
    const int rbase = blockIdx.x * 64;

    #pragma unroll
    for (int j = 0; j < 4; j++) cpa16(ws + tid * 4 + j * 1024, Ww + tid * 4 + j * 1024);
    CP_COMMIT();

    for (int idx = tid; idx < 64 * 32; idx += 256) {
        int r = idx >> 5, seg = idx & 31, rg = rbase + r;
        float4 v = make_float4(0.f, 0.f, 0.f, 0.f);
        if (rg < R) {
            int b = rg >> (DEPTH - 1), leaf = rg & (LEAVES - 1);
            v = *(const float4*)(x + ((size_t)b * NNODES + (LEAVES - 1) + leaf) * XDIM + seg * 4);
        }
        *(float4*)(xs + r * XDIM + seg * 4) = v;
    }

    const int tx = tid & 31, ty = tid >> 5;
    const int c0 = tx * 4;
    unsigned long long acc[8][4];
    #pragma unroll
    for (int r = 0; r < 8; r++)
        #pragma unroll
        for (int c = 0; c < 4; c++) acc[r][c] = 0ULL;

    const int NT = XDIM / KT;  // 8
    for (int kt = 0; kt < NT; kt++) {
        CP_WAIT0();
        __syncthreads();
        if (kt + 1 < NT) {
            const float* src = Ww + (kt + 1) * KT * K2;
            float* dst = ws + ((kt + 1) & 1) * (KT * K2);
            #pragma unroll
            for (int j = 0; j < 4; j++) cpa16(dst + tid * 4 + j * 1024, src + tid * 4 + j * 1024);
            CP_COMMIT();
        }
        gemm_tile16<8, K2>(acc, xs, ty * 8, XDIM, kt * KT,
                           ws + (kt & 1) * (KT * K2), c0);
    }

    float biasA[4], biasB[4];
    #pragma unroll
    for (int c = 0; c < 4; c++) { biasA[c] = Wb[c0 + c]; biasB[c] = Wb[HDIM + c0 + c]; }
    #pragma unroll
    for (int r = 0; r < 8; r++) {
        int rg = rbase + ty * 8 + r;
        if (rg >= R) continue;
        float lo[4], hi[4];
        upk2(acc[r][0], lo[0], lo[1]); upk2(acc[r][1], lo[2], lo[3]);
        upk2(acc[r][2], hi[0], hi[1]); upk2(acc[r][3], hi[2], hi[3]);
        float o[4];
        #pragma unroll
        for (int c = 0; c < 4; c++)
            o[c] = (1.f - sigf(lo[c] + biasA[c])) * tanh_fast(hi[c] + biasB[c]);
        int b = rg >> (DEPTH - 1), leaf = rg & (LEAVES - 1);
        *(float4*)(h + ((size_t)b * NNODES + (LEAVES - 1) + leaf) * HDIM + c0) =
            make_float4(o[0], o[1], o[2], o[3]);
    }
}

// ---------------- one tree level (BM rows, THR threads) --------------------
template<int BM, int THR>
__global__ void __launch_bounds__(THR, 1)
level_kernel(float* __restrict__ h,
             const float* __restrict__ Ufw, const float* __restrict__ Ufb,
             const float* __restrict__ Uhw, const float* __restrict__ Uhb,
             int l, int R)
{
    const int cnt = 1 << l, start = cnt - 1;
    extern __shared__ float sm[];
    float* gbuf = sm;                        // BM*256 (hc, later g = f*hc)
    float* sbuf = sm + BM * K2;              // BM*128 (s = f_lo + f_hi)
    float* ws   = sm + BM * K2 + BM * HDIM;  // 2*16*256
    const int tid = threadIdx.x;
    const int rbase = blockIdx.x * BM;

    constexpr int CPW1 = (KT * K2 / 4) / THR;
    constexpr int CPW2 = (KT * HDIM / 4) / THR;

    #pragma unroll
    for (int j = 0; j < CPW1; j++)
        cpa16(ws + (tid + j * THR) * 4, Ufw + (tid + j * THR) * 4);
    CP_COMMIT();

    for (int idx = tid; idx < BM * 64; idx += THR) {
        int r = idx >> 6, seg = idx & 63, rg = rbase + r;
        float4 v = make_float4(0.f, 0.f, 0.f, 0.f);
        if (rg < R) {
            int b = rg >> l, i = rg & (cnt - 1);
            v = *(const float4*)(h + ((size_t)b * NNODES + (size_t)2 * (start + i) + 1) * HDIM + seg * 4);
        }
        *(float4*)(gbuf + r * K2 + seg * 4) = v;
    }

    // ---- phase 1: f = sigmoid(hc@Ufw+Ufb); g = f*hc (in place); s = f_lo+f_hi ----
    {
        const int tx = tid & 31, ty = tid >> 5;
        const int c0 = tx * 4, c1 = HDIM + c0;
        constexpr int TM = BM / (THR / 32);
        unsigned long long acc[TM][4];
        #pragma unroll
        for (int r = 0; r < TM; r++)
            #pragma unroll
            for (int c = 0; c < 4; c++) acc[r][c] = 0ULL;

        const int NT = K2 / KT;  // 16
        for (int kt = 0; kt < NT; kt++) {
            CP_WAIT0();
            __syncthreads();
            if (kt + 1 < NT) {
                const float* src = Ufw + (kt + 1) * KT * K2;
                float* dst = ws + ((kt + 1) & 1) * (KT * K2);
                #pragma unroll
                for (int j = 0; j < CPW1; j++)
                    cpa16(dst + (tid + j * THR) * 4, src + (tid + j * THR) * 4);
                CP_COMMIT();
            }
            gemm_tile16<TM, K2>(acc, gbuf, ty * TM, K2, kt * KT,
                                ws + (kt & 1) * (KT * K2), c0);
        }
        __syncthreads();   // all reads of hc done before overwriting with g

        // prefetch Uhw tile 0 (overlaps epilogue)
        #pragma unroll
        for (int j = 0; j < CPW2; j++)
            cpa16(ws + (tid + j * THR) * 4, Uhw + (tid + j * THR) * 4);
        CP_COMMIT();

        float biasA[4], biasB[4];
        #pragma unroll
        for (int c = 0; c < 4; c++) { biasA[c] = Ufb[c0 + c]; biasB[c] = Ufb[c1 + c]; }
        #pragma unroll
        for (int r = 0; r < TM; r++) {
            int row = ty * TM + r;
            float lo[4], hi[4];
            upk2(acc[r][0], lo[0], lo[1]); upk2(acc[r][1], lo[2], lo[3]);
            upk2(acc[r][2], hi[0], hi[1]); upk2(acc[r][3], hi[2], hi[3]);
            #pragma unroll
            for (int c = 0; c < 4; c++) {
                lo[c] = sigf(lo[c] + biasA[c]);
                hi[c] = sigf(hi[c] + biasB[c]);
            }
            float4* gA = (float4*)(gbuf + row * K2 + c0);
            float4* gB = (float4*)(gbuf + row * K2 + c1);
            float4 hA = *gA, hB = *gB;
            *gA = make_float4(lo[0] * hA.x, lo[1] * hA.y, lo[2] * hA.z, lo[3] * hA.w);
            *gB = make_float4(hi[0] * hB.x, hi[1] * hB.y, hi[2] * hB.z, hi[3] * hB.w);
            *(float4*)(sbuf + row * HDIM + c0) =
                make_float4(lo[0] + hi[0], lo[1] + hi[1], lo[2] + hi[2], lo[3] + hi[3]);
        }
    }

    // ---- phase 2: cand = tanh(g@Uhw+Uhb); h_new = cand*(1-s) + g1 + g2 ----
    {
        const int tx = tid & 15, ty = tid >> 4;
        const int c0 = tx * 4, c1 = HDIM / 2 + c0;
        constexpr int TM2 = BM / (THR / 16);
        unsigned long long acc[TM2][4];
        #pragma unroll
        for (int r = 0; r < TM2; r++)
            #pragma unroll
            for (int c = 0; c < 4; c++) acc[r][c] = 0ULL;

        const int NT = K2 / KT;  // 16
        for (int kt = 0; kt < NT; kt++) {
            CP_WAIT0();
            __syncthreads();   // first iter also publishes g/s writes
            if (kt + 1 < NT) {
                const float* src = Uhw + (kt + 1) * KT * HDIM;
                float* dst = ws + ((kt + 1) & 1) * (KT * HDIM);
                #pragma unroll
                for (int j = 0; j < CPW2; j++)
                    cpa16(dst + (tid + j * THR) * 4, src + (tid + j * THR) * 4);
                CP_COMMIT();
            }
            gemm_tile16<TM2, HDIM>(acc, gbuf, ty * TM2, K2, kt * KT,
                                   ws + (kt & 1) * (KT * HDIM), c0);
        }

        float biasA[4], biasB[4];
        #pragma unroll
        for (int c = 0; c < 4; c++) { biasA[c] = Uhb[c0 + c]; biasB[c] = Uhb[c1 + c]; }
        #pragma unroll
        for (int r = 0; r < TM2; r++) {
            int row = ty * TM2 + r, rg = rbase + row;
            if (rg >= R) continue;
            float lo[4], hi[4];
            upk2(acc[r][0], lo[0], lo[1]); upk2(acc[r][1], lo[2], lo[3]);
            upk2(acc[r][2], hi[0], hi[1]); upk2(acc[r][3], hi[2], hi[3]);
            float4 sA = *(const float4*)(sbuf + row * HDIM + c0);
            float4 sB = *(const float4*)(sbuf + row * HDIM + c1);
            float4 p1A = *(const float4*)(gbuf + row * K2 + c0);
            float4 p1B = *(const float4*)(gbuf + row * K2 + c1);
            float4 p2A = *(const float4*)(gbuf + row * K2 + HDIM + c0);
            float4 p2B = *(const float4*)(gbuf + row * K2 + HDIM + c1);
            float oA[4], oB[4];
            oA[0] = tanh_fast(lo[0] + biasA[0]) * (1.f - sA.x) + p1A.x + p2A.x;
            oA[1] = tanh_fast(lo[1] + biasA[1]) * (1.f - sA.y) + p1A.y + p2A.y;
            oA[2] = tanh_fast(lo[2] + biasA[2]) * (1.f - sA.z) + p1A.z + p2A.z;
            oA[3] = tanh_fast(lo[3] + biasA[3]) * (1.f - sA.w) + p1A.w + p2A.w;
            oB[0] = tanh_fast(hi[0] + biasB[0]) * (1.f - sB.x) + p1B.x + p2B.x;
            oB[1] = tanh_fast(hi[1] + biasB[1]) * (1.f - sB.y) + p1B.y + p2B.y;
            oB[2] = tanh_fast(hi[2] + biasB[2]) * (1.f - sB.z) + p1B.z + p2B.z;
            oB[3] = tanh_fast(hi[3] + biasB[3]) * (1.f - sB.w) + p1B.w + p2B.w;
            int b = rg >> l, i = rg & (cnt - 1);
            float* dst = h + ((size_t)b * NNODES + start + i) * HDIM;
            *(float4*)(dst + c0) = make_float4(oA[0], oA[1], oA[2], oA[3]);
            *(float4*)(dst + c1) = make_float4(oB[0], oB[1], oB[2], oB[3]);
        }
    }
}

extern "C" void kernel_launch(void* const* d_in, const int* in_sizes, int n_in,
                              void* d_out, int out_size)
{
    const float* x   = (const float*)d_in[0];
    const float* Ww  = (const float*)d_in[1];
    const float* Wb  = (const float*)d_in[2];
    const float* Ufw = (const float*)d_in[3];
    const float* Ufb = (const float*)d_in[4];
    const float* Uhw = (const float*)d_in[5];
    const float* Uhb = (const float*)d_in[6];
    float* h = (float*)d_out;

    const int Btot = (out_size / HDIM) / NNODES;

    const int smem_leaf = (64 * XDIM + 2 * KT * K2) * (int)sizeof(float);               // 64 KB
    const int smem_l128 = (128 * K2 + 128 * HDIM + 2 * KT * K2) * (int)sizeof(float);   // 224 KB
    const int smem_l16  = (16 * K2 + 16 * HDIM + 2 * KT * K2) * (int)sizeof(float);     // 56 KB

    static bool attr_done = false;
    if (!attr_done) {
        cudaFuncSetAttribute(leaf_kernel,            cudaFuncAttributeMaxDynamicSharedMemorySize, smem_leaf);
        cudaFuncSetAttribute(level_kernel<128, 512>, cudaFuncAttributeMaxDynamicSharedMemorySize, smem_l128);
        cudaFuncSetAttribute(level_kernel<16, 256>,  cudaFuncAttributeMaxDynamicSharedMemorySize, smem_l16);
        attr_done = true;
    }

    const int Rleaf = Btot * LEAVES;
    leaf_kernel<<<(Rleaf + 63) / 64, 256, smem_leaf>>>(h, x, Ww, Wb, Rleaf);

    for (int l = DEPTH - 2; l >= 0; l--) {
        int R = Btot << l;
        if (R >= 2048)
            level_kernel<128, 512><<<(R + 127) / 128, 512, smem_l128>>>(h, Ufw, Ufb, Uhw, Uhb, l, R);
        else
            level_kernel<16, 256><<<(R + 15) / 16, 256, smem_l16>>>(h, Ufw, Ufb, Uhw, Uhb, l, R);
    }
}

// round 15
// speedup vs baseline: 1.9604x; 1.0012x over previous
#include <cuda_runtime.h>

#define DEPTH   15
#define HDIM    128
#define XDIM    128
#define K2      256
#define NNODES  ((1 << DEPTH) - 1)
#define LEAVES  (1 << (DEPTH - 1))
#define KTL     16   // leaf k-tile
#define KTV     32   // level k-tile

__device__ __forceinline__ void upk2(unsigned long long v, float& x, float& y) {
    asm("mov.b64 {%0, %1}, %2;" : "=f"(x), "=f"(y) : "l"(v));
}
__device__ __forceinline__ unsigned long long pk2(float x, float y) {
    unsigned long long r;
    asm("mov.b64 %0, {%1, %2};" : "=l"(r) : "f"(x), "f"(y));
    return r;
}
__device__ __forceinline__ void fma2(unsigned long long& c, unsigned long long a,
                                     unsigned long long b) {
    asm("fma.rn.f32x2 %0, %1, %2, %0;" : "+l"(c) : "l"(a), "l"(b));
}
__device__ __forceinline__ float sigf(float x)      { return 1.0f / (1.0f + __expf(-x)); }
__device__ __forceinline__ float tanh_fast(float x) { return 2.0f / (1.0f + __expf(-2.0f * x)) - 1.0f; }

__device__ __forceinline__ void cpa16(float* dst, const float* src) {
    unsigned d = (unsigned)__cvta_generic_to_shared(dst);
    asm volatile("cp.async.ca.shared.global [%0], [%1], 16;" :: "r"(d), "l"(src));
}
#define CP_COMMIT() asm volatile("cp.async.commit_group;")
#define CP_WAIT0()  asm volatile("cp.async.wait_group 0;" ::: "memory")

// ---- non-pipelined 16-k tile (leaf kernel: 256 thr, 128-reg budget) -------
template<int TM, int WN>
__device__ __forceinline__ void gemm_tile16(
    unsigned long long (&acc)[TM][4],
    const float* __restrict__ abuf, int arow0, int astride, int kbase,
    const float* __restrict__ w, int c0)
{
    const int c1 = WN / 2 + c0;
    #pragma unroll
    for (int j = 0; j < 4; j++) {
        float4 a4[TM];
        #pragma unroll
        for (int r = 0; r < TM; r++)
            a4[r] = *(const float4*)(abuf + (arow0 + r) * astride + kbase + j * 4);
        #pragma unroll
        for (int kk = 0; kk < 4; kk++) {
            const float* wk = w + (j * 4 + kk) * WN;
            ulonglong2 wa = *(const ulonglong2*)(wk + c0);
            ulonglong2 wb = *(const ulonglong2*)(wk + c1);
            #pragma unroll
            for (int r = 0; r < TM; r++) {
                float a = (kk == 0) ? a4[r].x : (kk == 1) ? a4[r].y
                        : (kk == 2) ? a4[r].z : a4[r].w;
                unsigned long long aa = pk2(a, a);
                fma2(acc[r][0], wa.x, aa); fma2(acc[r][1], wa.y, aa);
                fma2(acc[r][2], wb.x, aa); fma2(acc[r][3], wb.y, aa);
            }
        }
    }
}

// ---- software-pipelined KTT-k tile (level kernels, 384 thr: 170-reg cap) --
// weights prefetched k+1 ahead, acts prefetched one 4-k group ahead
template<int TM, int WN, int KTT>
__device__ __forceinline__ void gemm_tile_pl(
    unsigned long long (&acc)[TM][4],
    const float* __restrict__ abuf, int arow0, int astride, int kbase,
    const float* __restrict__ w, int c0)
{
    const int c1 = WN / 2 + c0;
    float4 aC[TM], aN[TM];
    #pragma unroll
    for (int r = 0; r < TM; r++)
        aC[r] = *(const float4*)(abuf + (arow0 + r) * astride + kbase);
    ulonglong2 wa = *(const ulonglong2*)(w + c0);
    ulonglong2 wb = *(const ulonglong2*)(w + c1);
    #pragma unroll
    for (int k = 0; k < KTT; k++) {
        ulonglong2 wan, wbn;
        if (k + 1 < KTT) {
            wan = *(const ulonglong2*)(w + (k + 1) * WN + c0);
            wbn = *(const ulonglong2*)(w + (k + 1) * WN + c1);
        }
        if ((k & 3) == 0 && k + 4 < KTT) {
            #pragma unroll
            for (int r = 0; r < TM; r++)
                aN[r] = *(const float4*)(abuf + (arow0 + r) * astride + kbase + k + 4);
        }
        #pragma unroll
        for (int r = 0; r < TM; r++) {
            float a = ((k & 3) == 0) ? aC[r].x : ((k & 3) == 1) ? aC[r].y
                    : ((k & 3) == 2) ? aC[r].z : aC[r].w;
            unsigned long long aa = pk2(a, a);
            fma2(acc[r][0], wa.x, aa); fma2(acc[r][1], wa.y, aa);
            fma2(acc[r][2], wb.x, aa); fma2(acc[r][3], wb.y, aa);
        }
        if ((k & 3) == 3) {
            #pragma unroll
            for (int r = 0; r < TM; r++) aC[r] = aN[r];
        }
        if (k + 1 < KTT) { wa = wan; wb = wbn; }
    }
}

// ---------------- leaf: h_leaf = (1-sig(a_lo))*tanh(a_hi), a = x@Ww + Wb ----
__global__ void __launch_bounds__(256, 2)
leaf_kernel(float* __restrict__ h, const float* __restrict__ x,
            const float* __restrict__ Ww, const float* __restrict__ Wb, int R)
{
    extern __shared__ float sm[];
    float* xs = sm;                 // 64*128
    float* ws = sm + 64 * XDIM;     // 2*16*256
    const int tid = threadIdx.x;
    const int rbase = blockIdx.x * 64;

    #pragma unroll
    for (int j = 0; j < 4; j++) cpa16(ws + tid * 4 + j * 1024, Ww + tid * 4 + j * 1024);
    CP_COMMIT();

    for (int idx = tid; idx < 64 * 32; idx += 256) {
        int r = idx >> 5, seg = idx & 31, rg = rbase + r;
        float4 v = make_float4(0.f, 0.f, 0.f, 0.f);
        if (rg < R) {
            int b = rg >> (DEPTH - 1), leaf = rg & (LEAVES - 1);
            v = *(const float4*)(x + ((size_t)b * NNODES + (LEAVES - 1) + leaf) * XDIM + seg * 4);
        }
        *(float4*)(xs + r * XDIM + seg * 4) = v;
    }

    const int tx = tid & 31, ty = tid >> 5;
    const int c0 = tx * 4;
    unsigned long long acc[8][4];
    #pragma unroll
    for (int r = 0; r < 8; r++)
        #pragma unroll
        for (int c = 0; c < 4; c++) acc[r][c] = 0ULL;

    const int NT = XDIM / KTL;  // 8
    for (int kt = 0; kt < NT; kt++) {
        CP_WAIT0();
        __syncthreads();
        if (kt + 1 < NT) {
            const float* src = Ww + (kt + 1) * KTL * K2;
            float* dst = ws + ((kt + 1) & 1) * (KTL * K2);
            #pragma unroll
            for (int j = 0; j < 4; j++) cpa16(dst + tid * 4 + j * 1024, src + tid * 4 + j * 1024);
            CP_COMMIT();
        }
        gemm_tile16<8, K2>(acc, xs, ty * 8, XDIM, kt * KTL,
                           ws + (kt & 1) * (KTL * K2), c0);
    }

    float biasA[4], biasB[4];
    #pragma unroll
    for (int c = 0; c < 4; c++) { biasA[c] = Wb[c0 + c]; biasB[c] = Wb[HDIM + c0 + c]; }
    #pragma unroll
    for (int r = 0; r < 8; r++) {
        int rg = rbase + ty * 8 + r;
        if (rg >= R) continue;
        float lo[4], hi[4];
        upk2(acc[r][0], lo[0], lo[1]); upk2(acc[r][1], lo[2], lo[3]);
        upk2(acc[r][2], hi[0], hi[1]); upk2(acc[r][3], hi[2], hi[3]);
        float o[4];
        #pragma unroll
        for (int c = 0; c < 4; c++)
            o[c] = (1.f - sigf(lo[c] + biasA[c])) * tanh_fast(hi[c] + biasB[c]);
        int b = rg >> (DEPTH - 1), leaf = rg & (LEAVES - 1);
        *(float4*)(h + ((size_t)b * NNODES + (LEAVES - 1) + leaf) * HDIM + c0) =
            make_float4(o[0], o[1], o[2], o[3]);
    }
}

// ---------------- one tree level (BM rows, THR threads, KTV=32 k-tiles) ----
template<int BM, int THR>
__global__ void __launch_bounds__(THR, 1)
level_kernel(float* __restrict__ h,
             const float* __restrict__ Ufw, const float* __restrict__ Ufb,
             const float* __restrict__ Uhw, const float* __restrict__ Uhb,
             int l, int R)
{
    const int cnt = 1 << l, start = cnt - 1;
    extern __shared__ float sm[];
    float* gbuf = sm;                        // BM*256 (hc, later g = f*hc)
    float* sbuf = sm + BM * K2;              // BM*128 (s = f_lo + f_hi)
    float* ws   = sm + BM * K2 + BM * HDIM;  // 2*KTV*256
    const int tid = threadIdx.x;
    const int rbase = blockIdx.x * BM;

    const int T1F4 = KTV * K2 / 4;    // 2048 float4 per Uf tile
    const int T2F4 = KTV * HDIM / 4;  // 1024 float4 per Uh tile

    for (int i = tid; i < T1F4; i += THR) cpa16(ws + i * 4, Ufw + i * 4);
    CP_COMMIT();

    for (int idx = tid; idx < BM * 64; idx += THR) {
        int r = idx >> 6, seg = idx & 63, rg = rbase + r;
        float4 v = make_float4(0.f, 0.f, 0.f, 0.f);
        if (rg < R) {
            int b = rg >> l, i = rg & (cnt - 1);
            v = *(const float4*)(h + ((size_t)b * NNODES + (size_t)2 * (start + i) + 1) * HDIM + seg * 4);
        }
        *(float4*)(gbuf + r * K2 + seg * 4) = v;
    }

    // ---- phase 1: f = sigmoid(hc@Ufw+Ufb); g = f*hc (in place); s = f_lo+f_hi ----
    {
        const int tx = tid & 31, ty = tid >> 5;
        const int c0 = tx * 4, c1 = HDIM + c0;
        constexpr int TM = BM / (THR / 32);
        unsigned long long acc[TM][4];
        #pragma unroll
        for (int r = 0; r < TM; r++)
            #pragma unroll
            for (int c = 0; c < 4; c++) acc[r][c] = 0ULL;

        const int NT = K2 / KTV;  // 8
        for (int kt = 0; kt < NT; kt++) {
            CP_WAIT0();
            __syncthreads();
            if (kt + 1 < NT) {
                const float* src = Ufw + (kt + 1) * KTV * K2;
                float* dst = ws + ((kt + 1) & 1) * (KTV * K2);
                for (int i = tid; i < T1F4; i += THR) cpa16(dst + i * 4, src + i * 4);
                CP_COMMIT();
            }
            gemm_tile_pl<TM, K2, KTV>(acc, gbuf, ty * TM, K2, kt * KTV,
                                      ws + (kt & 1) * (KTV * K2), c0);
        }
        __syncthreads();   // all reads of hc done before overwriting with g

        // prefetch Uhw tile 0 (overlaps epilogue)
        for (int i = tid; i < T2F4; i += THR) cpa16(ws + i * 4, Uhw + i * 4);
        CP_COMMIT();

        float biasA[4], biasB[4];
        #pragma unroll
        for (int c = 0; c < 4; c++) { biasA[c] = Ufb[c0 + c]; biasB[c] = Ufb[c1 + c]; }
        #pragma unroll
        for (int r = 0; r < TM; r++) {
            int row = ty * TM + r;
            float lo[4], hi[4];
            upk2(acc[r][0], lo[0], lo[1]); upk2(acc[r][1], lo[2], lo[3]);
            upk2(acc[r][2], hi[0], hi[1]); upk2(acc[r][3], hi[2], hi[3]);
            #pragma unroll
            for (int c = 0; c < 4; c++) {
                lo[c] = sigf(lo[c] + biasA[c]);
                hi[c] = sigf(hi[c] + biasB[c]);
            }
            float4* gA = (float4*)(gbuf + row * K2 + c0);
            float4* gB = (float4*)(gbuf + row * K2 + c1);
            float4 hA = *gA, hB = *gB;
            *gA = make_float4(lo[0] * hA.x, lo[1] * hA.y, lo[2] * hA.z, lo[3] * hA.w);
            *gB = make_float4(hi[0] * hB.x, hi[1] * hB.y, hi[2] * hB.z, hi[3] * hB.w);
            *(float4*)(sbuf + row * HDIM + c0) =
                make_float4(lo[0] + hi[0], lo[1] + hi[1], lo[2] + hi[2], lo[3] + hi[3]);
        }
    }

    // ---- phase 2: cand = tanh(g@Uhw+Uhb); h_new = cand*(1-s) + g1 + g2 ----
    {
        const int tx = tid & 15, ty = tid >> 4;
        const int c0 = tx * 4, c1 = HDIM / 2 + c0;
        constexpr int TM2 = BM / (THR / 16);
        unsigned long long acc[TM2][4];
        #pragma unroll
        for (int r = 0; r < TM2; r++)
            #pragma unroll
            for (int c = 0; c < 4; c++) acc[r][c] = 0ULL;

        const int NT = K2 / KTV;  // 8
        for (int kt = 0; kt < NT; kt++) {
            CP_WAIT0();
            __syncthreads();   // first iter also publishes g/s writes
            if (kt + 1 < NT) {
                const float* src = Uhw + (kt + 1) * KTV * HDIM;
                float* dst = ws + ((kt + 1) & 1) * (KTV * HDIM);
                for (int i = tid; i < T2F4; i += THR) cpa16(dst + i * 4, src + i * 4);
                CP_COMMIT();
            }
            gemm_tile_pl<TM2, HDIM, KTV>(acc, gbuf, ty * TM2, K2, kt * KTV,
                                         ws + (kt & 1) * (KTV * HDIM), c0);
        }

        float biasA[4], biasB[4];
        #pragma unroll
        for (int c = 0; c < 4; c++) { biasA[c] = Uhb[c0 + c]; biasB[c] = Uhb[c1 + c]; }
        #pragma unroll
        for (int r = 0; r < TM2; r++) {
            int row = ty * TM2 + r, rg = rbase + row;
            if (rg >= R) continue;
            float lo[4], hi[4];
            upk2(acc[r][0], lo[0], lo[1]); upk2(acc[r][1], lo[2], lo[3]);
            upk2(acc[r][2], hi[0], hi[1]); upk2(acc[r][3], hi[2], hi[3]);
            float4 sA = *(const float4*)(sbuf + row * HDIM + c0);
            float4 sB = *(const float4*)(sbuf + row * HDIM + c1);
            float4 p1A = *(const float4*)(gbuf + row * K2 + c0);
            float4 p1B = *(const float4*)(gbuf + row * K2 + c1);
            float4 p2A = *(const float4*)(gbuf + row * K2 + HDIM + c0);
            float4 p2B = *(const float4*)(gbuf + row * K2 + HDIM + c1);
            float oA[4], oB[4];
            oA[0] = tanh_fast(lo[0] + biasA[0]) * (1.f - sA.x) + p1A.x + p2A.x;
            oA[1] = tanh_fast(lo[1] + biasA[1]) * (1.f - sA.y) + p1A.y + p2A.y;
            oA[2] = tanh_fast(lo[2] + biasA[2]) * (1.f - sA.z) + p1A.z + p2A.z;
            oA[3] = tanh_fast(lo[3] + biasA[3]) * (1.f - sA.w) + p1A.w + p2A.w;
            oB[0] = tanh_fast(hi[0] + biasB[0]) * (1.f - sB.x) + p1B.x + p2B.x;
            oB[1] = tanh_fast(hi[1] + biasB[1]) * (1.f - sB.y) + p1B.y + p2B.y;
            oB[2] = tanh_fast(hi[2] + biasB[2]) * (1.f - sB.z) + p1B.z + p2B.z;
            oB[3] = tanh_fast(hi[3] + biasB[3]) * (1.f - sB.w) + p1B.w + p2B.w;
            int b = rg >> l, i = rg & (cnt - 1);
            float* dst = h + ((size_t)b * NNODES + start + i) * HDIM;
            *(float4*)(dst + c0) = make_float4(oA[0], oA[1], oA[2], oA[3]);
            *(float4*)(dst + c1) = make_float4(oB[0], oB[1], oB[2], oB[3]);
        }
    }
}

extern "C" void kernel_launch(void* const* d_in, const int* in_sizes, int n_in,
                              void* d_out, int out_size)
{
    const float* x   = (const float*)d_in[0];
    const float* Ww  = (const float*)d_in[1];
    const float* Wb  = (const float*)d_in[2];
    const float* Ufw = (const float*)d_in[3];
    const float* Ufb = (const float*)d_in[4];
    const float* Uhw = (const float*)d_in[5];
    const float* Uhb = (const float*)d_in[6];
    float* h = (float*)d_out;

    const int Btot = (out_size / HDIM) / NNODES;

    const int smem_leaf = (64 * XDIM + 2 * KTL * K2) * (int)sizeof(float);              // 64 KB
    const int smem_l96  = (96 * K2 + 96 * HDIM + 2 * KTV * K2) * (int)sizeof(float);    // 208 KB
    const int smem_l16  = (16 * K2 + 16 * HDIM + 2 * KTV * K2) * (int)sizeof(float);    // 88 KB

    static bool attr_done = false;
    if (!attr_done) {
        cudaFuncSetAttribute(leaf_kernel,           cudaFuncAttributeMaxDynamicSharedMemorySize, smem_leaf);
        cudaFuncSetAttribute(level_kernel<96, 384>, cudaFuncAttributeMaxDynamicSharedMemorySize, smem_l96);
        cudaFuncSetAttribute(level_kernel<16, 256>, cudaFuncAttributeMaxDynamicSharedMemorySize, smem_l16);
        attr_done = true;
    }

    const int Rleaf = Btot * LEAVES;
    leaf_kernel<<<(Rleaf + 63) / 64, 256, smem_leaf>>>(h, x, Ww, Wb, Rleaf);

    for (int l = DEPTH - 2; l >= 0; l--) {
        int R = Btot << l;
        if (R >= 2048)
            level_kernel<96, 384><<<(R + 95) / 96, 384, smem_l96>>>(h, Ufw, Ufb, Uhw, Uhb, l, R);
        else
            level_kernel<16, 256><<<(R + 15) / 16, 256, smem_l16>>>(h, Ufw, Ufb, Uhw, Uhb, l, R);
    }
}